// round 7
// baseline (speedup 1.0000x reference)
#include <cuda_runtime.h>
#include <cstdint>

// Perona-Malik single diffusion step — ROWS=2 at max occupancy, loads via
// front-batched LDG.128, stores staged in smem and drained with
// cp.async.bulk (TMA 1D) as whole 4KB rows.
// out = clamp(image + g * exp(-g^2/K^2) * dt, 0, 1)
// g   = 5-point Laplacian with ReflectionPad2d(1); K=0.1 (1/K^2=100), dt=0.15

#define W 1024
#define H 1024
#define W4 (W / 4)
#define ROWS 2

__global__ __launch_bounds__(256, 8)
void pm_kernel(const float* __restrict__ in, float* __restrict__ out) {
    __shared__ __align__(128) float4 sbuf[ROWS][256];

    const int y0 = blockIdx.x * ROWS;      // first output row of this block
    const int n  = blockIdx.y;             // image index
    const int t  = threadIdx.x;            // float4 column 0..255
    const int lane = t & 31;

    const float* img = in  + (size_t)n * (W * H);
    float*       o   = out + (size_t)n * (W * H);

    // Rows y0-1 .. y0+2, reflect at volume edges (no edge duplication):
    // -1 -> 1, H -> H-2. Front-batched: 4 consecutive LDG.128 per thread.
    float4 rr[ROWS + 2];
    #pragma unroll
    for (int i = 0; i < ROWS + 2; i++) {
        int yy = y0 - 1 + i;
        yy = (yy < 0) ? 1 : ((yy >= H) ? (2 * H - 2 - yy) : yy);
        rr[i] = ((const float4*)(img + (size_t)yy * W))[t];
    }

    const float* rowc = img + (size_t)y0 * W;

    #pragma unroll
    for (int i = 0; i < ROWS; i++) {
        const float4 u = rr[i];
        const float4 c = rr[i + 1];
        const float4 d = rr[i + 2];

        // Horizontal halo via warp shuffle; warp-edge lanes fall back to a
        // scalar global load (L1 hit); image-edge lanes use reflection.
        float left  = __shfl_up_sync(0xffffffffu, c.w, 1);
        float right = __shfl_down_sync(0xffffffffu, c.x, 1);
        if (lane == 0)
            left  = (t == 0)      ? c.y : rowc[4 * t - 1];
        if (lane == 31)
            right = (t == W4 - 1) ? c.z : rowc[4 * t + 4];

        float4 g;
        g.x = u.x + d.x + left + c.y  - 4.0f * c.x;
        g.y = u.y + d.y + c.x  + c.z  - 4.0f * c.y;
        g.z = u.z + d.z + c.y  + c.w  - 4.0f * c.z;
        g.w = u.w + d.w + c.z  + right - 4.0f * c.w;

        float4 r;
        float gg, co, v;
        gg = g.x; co = __expf(-gg * gg * 100.0f);
        v = fmaf(gg * co, 0.15f, c.x); r.x = fminf(fmaxf(v, 0.0f), 1.0f);
        gg = g.y; co = __expf(-gg * gg * 100.0f);
        v = fmaf(gg * co, 0.15f, c.y); r.y = fminf(fmaxf(v, 0.0f), 1.0f);
        gg = g.z; co = __expf(-gg * gg * 100.0f);
        v = fmaf(gg * co, 0.15f, c.z); r.z = fminf(fmaxf(v, 0.0f), 1.0f);
        gg = g.w; co = __expf(-gg * gg * 100.0f);
        v = fmaf(gg * co, 0.15f, c.w); r.w = fminf(fmaxf(v, 0.0f), 1.0f);

        sbuf[i][t] = r;
        rowc += W;
    }

    __syncthreads();

    // One thread drains both 4KB rows as TMA bulk copies (smem -> global).
    if (t == 0) {
        asm volatile("fence.proxy.async.shared::cta;" ::: "memory");
        #pragma unroll
        for (int i = 0; i < ROWS; i++) {
            uint32_t saddr;
            asm("{ .reg .u64 tmp; cvta.to.shared.u64 tmp, %1; cvt.u32.u64 %0, tmp; }"
                : "=r"(saddr) : "l"(&sbuf[i][0]));
            const float* gdst = o + (size_t)(y0 + i) * W;
            asm volatile(
                "cp.async.bulk.global.shared::cta.bulk_group [%0], [%1], %2;"
                :: "l"(gdst), "r"(saddr), "n"(W * 4) : "memory");
        }
        asm volatile("cp.async.bulk.commit_group;" ::: "memory");
        // Wait until smem has been read out (not full DRAM commit) before the
        // CTA may exit and its smem be reallocated.
        asm volatile("cp.async.bulk.wait_group.read 0;" ::: "memory");
    }
}

extern "C" void kernel_launch(void* const* d_in, const int* in_sizes, int n_in,
                              void* d_out, int out_size) {
    const float* image = (const float*)d_in[0];
    // d_in[1] is the fixed 3x3 Laplace kernel; hardcoded in pm_kernel.
    float* out = (float*)d_out;

    const int n_images = in_sizes[0] / (W * H);   // 64
    dim3 grid(H / ROWS, n_images);
    pm_kernel<<<grid, 256>>>(image, out);
}

// round 8
// speedup vs baseline: 1.0724x; 1.0724x over previous
#include <cuda_runtime.h>
#include <cstdint>

// Perona-Malik single diffusion step — TMA bulk-load staging into smem,
// rolling-register compute from smem, direct streaming stores.
// out = clamp(image + g * exp(-g^2/K^2) * dt, 0, 1)
// g   = 5-point Laplacian with ReflectionPad2d(1); K=0.1 (1/K^2=100), dt=0.15

#define W 1024
#define H 1024
#define W4 (W / 4)
#define ROWS 4
#define SROWS (ROWS + 2)

__device__ __forceinline__ void stcs4(float4* p, float4 v) {
    asm volatile("st.global.cs.v4.f32 [%0], {%1,%2,%3,%4};"
                 :: "l"(p), "f"(v.x), "f"(v.y), "f"(v.z), "f"(v.w) : "memory");
}

__global__ __launch_bounds__(256, 6)
void pm_kernel(const float* __restrict__ in, float* __restrict__ out) {
    __shared__ __align__(16) float srows[SROWS][W];   // 24 KB
    __shared__ __align__(8) unsigned long long mbar;

    const int y0 = blockIdx.x * ROWS;      // first output row of this block
    const int n  = blockIdx.y;             // image index
    const int t  = threadIdx.x;            // float4 column 0..255

    const float* img = in  + (size_t)n * (W * H);
    float*       o   = out + (size_t)n * (W * H);

    const uint32_t mbar_addr = (uint32_t)__cvta_generic_to_shared(&mbar);

    if (t == 0) {
        asm volatile("mbarrier.init.shared.b64 [%0], 1;" :: "r"(mbar_addr));
    }
    __syncthreads();

    // Elected thread: expect full 24KB, then issue 6 bulk row copies
    // (global -> smem). Rows reflected at volume edges (-1 -> 1, H -> H-2).
    if (t == 0) {
        asm volatile("mbarrier.arrive.expect_tx.shared.b64 _, [%0], %1;"
                     :: "r"(mbar_addr), "r"((uint32_t)(SROWS * W * 4))
                     : "memory");
        #pragma unroll
        for (int j = 0; j < SROWS; j++) {
            int yy = y0 - 1 + j;
            yy = (yy < 0) ? 1 : ((yy >= H) ? (2 * H - 2 - yy) : yy);
            const uint32_t daddr =
                (uint32_t)__cvta_generic_to_shared(&srows[j][0]);
            const float* src = img + (size_t)yy * W;
            asm volatile(
                "cp.async.bulk.shared::cta.global.mbarrier::complete_tx::bytes "
                "[%0], [%1], %2, [%3];"
                :: "r"(daddr), "l"(src), "n"(W * 4), "r"(mbar_addr)
                : "memory");
        }
    }

    // All threads wait for the staged tile (phase parity 0).
    asm volatile(
        "{\n\t"
        ".reg .pred P;\n\t"
        "WAIT_%=:\n\t"
        "mbarrier.try_wait.parity.acquire.cta.shared::cta.b64 P, [%0], 0, 0x989680;\n\t"
        "@P bra.uni DONE_%=;\n\t"
        "bra.uni WAIT_%=;\n\t"
        "DONE_%=:\n\t"
        "}"
        :: "r"(mbar_addr) : "memory");

    // Rolling-register walk down the strip: 1 LDS.128 + 2 scalar LDS per row.
    float4 a = *(const float4*)&srows[0][4 * t];   // row above
    float4 b = *(const float4*)&srows[1][4 * t];   // center row

    #pragma unroll
    for (int i = 0; i < ROWS; i++) {
        const float4 d = *(const float4*)&srows[i + 2][4 * t];

        // Horizontal halo straight from smem; image-edge reflection uses the
        // in-register neighbors (left of col0 reflects to col1 = b.y, etc).
        const float left  = (t == 0)      ? b.y : srows[i + 1][4 * t - 1];
        const float right = (t == W4 - 1) ? b.z : srows[i + 1][4 * t + 4];

        float4 g;
        g.x = a.x + d.x + left + b.y  - 4.0f * b.x;
        g.y = a.y + d.y + b.x  + b.z  - 4.0f * b.y;
        g.z = a.z + d.z + b.y  + b.w  - 4.0f * b.z;
        g.w = a.w + d.w + b.z  + right - 4.0f * b.w;

        float4 r;
        float gg, co, v;
        gg = g.x; co = __expf(-gg * gg * 100.0f);
        v = fmaf(gg * co, 0.15f, b.x); r.x = fminf(fmaxf(v, 0.0f), 1.0f);
        gg = g.y; co = __expf(-gg * gg * 100.0f);
        v = fmaf(gg * co, 0.15f, b.y); r.y = fminf(fmaxf(v, 0.0f), 1.0f);
        gg = g.z; co = __expf(-gg * gg * 100.0f);
        v = fmaf(gg * co, 0.15f, b.z); r.z = fminf(fmaxf(v, 0.0f), 1.0f);
        gg = g.w; co = __expf(-gg * gg * 100.0f);
        v = fmaf(gg * co, 0.15f, b.w); r.w = fminf(fmaxf(v, 0.0f), 1.0f);

        stcs4((float4*)(o + (size_t)(y0 + i) * W) + t, r);

        a = b; b = d;
    }
}

extern "C" void kernel_launch(void* const* d_in, const int* in_sizes, int n_in,
                              void* d_out, int out_size) {
    const float* image = (const float*)d_in[0];
    // d_in[1] is the fixed 3x3 Laplace kernel; hardcoded in pm_kernel.
    float* out = (float*)d_out;

    const int n_images = in_sizes[0] / (W * H);   // 64
    dim3 grid(H / ROWS, n_images);
    pm_kernel<<<grid, 256>>>(image, out);
}